// round 14
// baseline (speedup 1.0000x reference)
#include <cuda_runtime.h>
#include <cuda_bf16.h>
#include <math.h>
#include <stdint.h>

// Problem constants
#define BATCH 4
#define SEQ_N 4096
#define SEQ_M 256
#define DIM 1024
#define CTX_DIM 768
#define HEADS 16
#define HD 64
#define ROWS_X (BATCH * SEQ_N)      // 16384
#define ROWS_C (BATCH * SEQ_M)      // 1024

// Scratch (device globals)
__device__ __nv_bfloat16 g_Ah[ROWS_X * DIM];
__device__ __nv_bfloat16 g_Al[ROWS_X * DIM];
__device__ __nv_bfloat16 g_Ch[ROWS_C * CTX_DIM];
__device__ __nv_bfloat16 g_Cl[ROWS_C * CTX_DIM];
__device__ __nv_bfloat16 g_Bqh[DIM * DIM];      // Wq^T
__device__ __nv_bfloat16 g_Bql[DIM * DIM];
__device__ __nv_bfloat16 g_Bh[2048 * 1024];     // [Wk^T ; Wv^T]
__device__ __nv_bfloat16 g_Bl[2048 * 1024];
__device__ __nv_bfloat16 g_Boh[DIM * DIM];      // Wo^T
__device__ __nv_bfloat16 g_Bol[DIM * DIM];
__device__ __nv_bfloat16 g_Qh[ROWS_X * DIM];
__device__ __nv_bfloat16 g_Ql[ROWS_X * DIM];
__device__ __nv_bfloat16 g_Kh[ROWS_C * DIM];
__device__ __nv_bfloat16 g_Kl[ROWS_C * DIM];
__device__ __nv_bfloat16 g_Vh[ROWS_C * DIM];
__device__ __nv_bfloat16 g_Vl[ROWS_C * DIM];

// ---------------------------------------------------------------------------
// PTX helpers (sm_80+ portable)
// ---------------------------------------------------------------------------
__device__ __forceinline__ uint32_t smem_u32(const void* p) {
    uint32_t a;
    asm("{ .reg .u64 t; cvta.to.shared.u64 t, %1; cvt.u32.u64 %0, t; }" : "=r"(a) : "l"(p));
    return a;
}
#define CP_ASYNC16(dst, src) \
    asm volatile("cp.async.cg.shared.global [%0], [%1], 16;" :: "r"(dst), "l"(src))
#define CP_COMMIT() asm volatile("cp.async.commit_group;" ::: "memory")
#define CP_WAIT(n)  asm volatile("cp.async.wait_group %0;" :: "n"(n) : "memory")

#define LDM_X4(r0, r1, r2, r3, a) \
    asm volatile("ldmatrix.sync.aligned.m8n8.x4.shared.b16 {%0,%1,%2,%3}, [%4];" \
                 : "=r"(r0), "=r"(r1), "=r"(r2), "=r"(r3) : "r"(a))
#define LDM_X4T(r0, r1, r2, r3, a) \
    asm volatile("ldmatrix.sync.aligned.m8n8.x4.trans.shared.b16 {%0,%1,%2,%3}, [%4];" \
                 : "=r"(r0), "=r"(r1), "=r"(r2), "=r"(r3) : "r"(a))

#define MMA_BF16(d, a, b) \
    asm volatile("mma.sync.aligned.m16n8k16.row.col.f32.bf16.bf16.f32 " \
                 "{%0,%1,%2,%3},{%4,%5,%6,%7},{%8,%9},{%0,%1,%2,%3};" \
                 : "+f"((d)[0]), "+f"((d)[1]), "+f"((d)[2]), "+f"((d)[3]) \
                 : "r"((a)[0]), "r"((a)[1]), "r"((a)[2]), "r"((a)[3]), \
                   "r"((b)[0]), "r"((b)[1]))

__device__ __forceinline__ void split2(float x, float y, uint32_t& h, uint32_t& l) {
    __nv_bfloat162 hb = __float22bfloat162_rn(make_float2(x, y));
    float2 hf = __bfloat1622float2(hb);
    __nv_bfloat162 lb = __float22bfloat162_rn(make_float2(x - hf.x, y - hf.y));
    h = *(uint32_t*)&hb;
    l = *(uint32_t*)&lb;
}

// ---------------------------------------------------------------------------
// fp32 -> bf16 hi/lo split
// ---------------------------------------------------------------------------
__global__ void split_kernel(const float* __restrict__ X, __nv_bfloat16* __restrict__ Xh,
                             __nv_bfloat16* __restrict__ Xl, int n4)
{
    int i = blockIdx.x * blockDim.x + threadIdx.x;
    if (i >= n4) return;
    float4 v = ((const float4*)X)[i];
    float a[4] = {v.x, v.y, v.z, v.w};
    __nv_bfloat16 h[4], l[4];
    #pragma unroll
    for (int j = 0; j < 4; j++) {
        h[j] = __float2bfloat16(a[j]);
        l[j] = __float2bfloat16(a[j] - __bfloat162float(h[j]));
    }
    __nv_bfloat162* Hp = (__nv_bfloat162*)(Xh + 4 * (size_t)i);
    __nv_bfloat162* Lp = (__nv_bfloat162*)(Xl + 4 * (size_t)i);
    Hp[0] = __nv_bfloat162(h[0], h[1]); Hp[1] = __nv_bfloat162(h[2], h[3]);
    Lp[0] = __nv_bfloat162(l[0], l[1]); Lp[1] = __nv_bfloat162(l[2], l[3]);
}

// ---------------------------------------------------------------------------
// W[K][N] -> Th/Tl[N][K] bf16 hi/lo (transpose + split)
// ---------------------------------------------------------------------------
__global__ void transpose_split_kernel(const float* __restrict__ W, __nv_bfloat16* __restrict__ Th,
                                       __nv_bfloat16* __restrict__ Tl, int K, int N)
{
    __shared__ float tile[32][33];
    int n0 = blockIdx.x * 32, k0 = blockIdx.y * 32;
    int tx = threadIdx.x, ty = threadIdx.y;
    #pragma unroll
    for (int j = ty; j < 32; j += 8)
        tile[j][tx] = W[(size_t)(k0 + j) * N + n0 + tx];
    __syncthreads();
    #pragma unroll
    for (int j = ty; j < 32; j += 8) {
        float v = tile[tx][j];
        __nv_bfloat16 h = __float2bfloat16(v);
        __nv_bfloat16 l = __float2bfloat16(v - __bfloat162float(h));
        size_t o = (size_t)(n0 + j) * K + k0 + tx;
        Th[o] = h; Tl[o] = l;
    }
}

// ---------------------------------------------------------------------------
// HMMA bf16-split GEMM (R10-proven math): 128x128x32, 8 warps of 64x32,
// 2-stage cp.async, 2 CTAs/SM. rowOff shifts the M-tile origin so the grid
// can be split into independent row-halves. SPLIT=1 routes cols>=1024 to D.
// ---------------------------------------------------------------------------
#define BM 128
#define BN 128
#define BK 32
#define PITCH 80
#define TILE_B (128 * PITCH)
#define STAGE  (4 * TILE_B)
#define GEMM_SMEM (2 * STAGE)

template<int SPLIT>
__global__ void __launch_bounds__(256, 2)
gemm_hmma_kernel(const __nv_bfloat16* __restrict__ Ah, const __nv_bfloat16* __restrict__ Al,
                 const __nv_bfloat16* __restrict__ Bh, const __nv_bfloat16* __restrict__ Bl,
                 float* __restrict__ C, __nv_bfloat16* __restrict__ Ch,
                 __nv_bfloat16* __restrict__ Cl, __nv_bfloat16* __restrict__ Dh,
                 __nv_bfloat16* __restrict__ Dl, int K, int rowOff)
{
    extern __shared__ __align__(128) char sm[];
    const uint32_t sb = smem_u32(sm);
    const int t = threadIdx.x, wid = t >> 5, lane = t & 31;
    const int m0 = rowOff + blockIdx.y * BM, n0 = blockIdx.x * BN;
    const int NC = K / BK;
    const int wr = wid & 1, wc = wid >> 1;

    const int lr0 = t >> 2;
    const int lch = t & 3;

    const int g = lane >> 3, lrw = lane & 7;
    const uint32_t a_off = (uint32_t)(((g & 1) * 8 + lrw) * PITCH + (g >> 1) * 16);
    const uint32_t b_off = (uint32_t)(((g >> 1) * 8 + lrw) * PITCH + (g & 1) * 16);

    float acc[4][4][4];
    #pragma unroll
    for (int mt = 0; mt < 4; mt++)
        #pragma unroll
        for (int ng = 0; ng < 4; ng++)
            #pragma unroll
            for (int q = 0; q < 4; q++) acc[mt][ng][q] = 0.0f;

    auto issue = [&](int c) {
        const int buf = c & 1;
        const uint32_t stg = sb + buf * STAGE;
        const int kt = c * BK;
        #pragma unroll
        for (int i = 0; i < 2; i++) {
            const int r = lr0 + i * 64;
            const uint32_t doff = (uint32_t)(r * PITCH + lch * 16);
            const size_t sa = (size_t)(m0 + r) * K + kt + lch * 8;
            const size_t sbi = (size_t)(n0 + r) * K + kt + lch * 8;
            CP_ASYNC16(stg + doff,               Ah + sa);
            CP_ASYNC16(stg + TILE_B + doff,      Al + sa);
            CP_ASYNC16(stg + 2 * TILE_B + doff,  Bh + sbi);
            CP_ASYNC16(stg + 3 * TILE_B + doff,  Bl + sbi);
        }
        CP_COMMIT();
    };

    issue(0);

    for (int c = 0; c < NC; c++) {
        if (c + 1 < NC) { issue(c + 1); CP_WAIT(1); }
        else            { CP_WAIT(0); }
        __syncthreads();

        const uint32_t stg = sb + (c & 1) * STAGE;
        const uint32_t aH = stg + (uint32_t)(wr * 64) * PITCH;
        const uint32_t aL = aH + TILE_B;
        const uint32_t bH = stg + 2 * TILE_B + (uint32_t)(wc * 32) * PITCH;
        const uint32_t bL = bH + TILE_B;

        #pragma unroll
        for (int ks = 0; ks < 2; ks++) {
            const uint32_t kb = (uint32_t)(ks * 32);
            uint32_t fAh[4][4], fAl[4][4], fBh[4][2], fBl[4][2];
            #pragma unroll
            for (int mt = 0; mt < 4; mt++) {
                uint32_t ad = aH + (uint32_t)(mt * 16) * PITCH + kb + a_off;
                LDM_X4(fAh[mt][0], fAh[mt][1], fAh[mt][2], fAh[mt][3], ad);
                uint32_t ad2 = aL + (uint32_t)(mt * 16) * PITCH + kb + a_off;
                LDM_X4(fAl[mt][0], fAl[mt][1], fAl[mt][2], fAl[mt][3], ad2);
            }
            #pragma unroll
            for (int nt = 0; nt < 2; nt++) {
                uint32_t bd = bH + (uint32_t)(nt * 16) * PITCH + kb + b_off;
                uint32_t r0, r1, r2, r3;
                LDM_X4(r0, r1, r2, r3, bd);
                fBh[nt * 2][0] = r0; fBh[nt * 2][1] = r1;
                fBh[nt * 2 + 1][0] = r2; fBh[nt * 2 + 1][1] = r3;
                uint32_t bd2 = bL + (uint32_t)(nt * 16) * PITCH + kb + b_off;
                LDM_X4(r0, r1, r2, r3, bd2);
                fBl[nt * 2][0] = r0; fBl[nt * 2][1] = r1;
                fBl[nt * 2 + 1][0] = r2; fBl[nt * 2 + 1][1] = r3;
            }
            #pragma unroll
            for (int mt = 0; mt < 4; mt++) {
                #pragma unroll
                for (int ng = 0; ng < 4; ng++) {
                    MMA_BF16(acc[mt][ng], fAh[mt], fBh[ng]);
                    MMA_BF16(acc[mt][ng], fAh[mt], fBl[ng]);
                    MMA_BF16(acc[mt][ng], fAl[mt], fBh[ng]);
                }
            }
        }
        __syncthreads();
    }

    const int row0 = m0 + wr * 64 + lane / 4;
    const int col0 = wc * 32 + (lane % 4) * 2;
    #pragma unroll
    for (int mt = 0; mt < 4; mt++) {
        #pragma unroll
        for (int ng = 0; ng < 4; ng++) {
            int gc = n0 + col0 + ng * 8;
            if (SPLIT) {
                __nv_bfloat16 *Hp, *Lp;
                if (gc < 1024) { Hp = Ch; Lp = Cl; }
                else           { Hp = Dh; Lp = Dl; gc -= 1024; }
                size_t o1 = (size_t)(row0 + mt * 16) * DIM + gc;
                size_t o2 = o1 + 8 * DIM;
                uint32_t h, l;
                split2(acc[mt][ng][0], acc[mt][ng][1], h, l);
                *(uint32_t*)(Hp + o1) = h; *(uint32_t*)(Lp + o1) = l;
                split2(acc[mt][ng][2], acc[mt][ng][3], h, l);
                *(uint32_t*)(Hp + o2) = h; *(uint32_t*)(Lp + o2) = l;
            } else {
                size_t o1 = (size_t)(row0 + mt * 16) * DIM + gc;
                size_t o2 = o1 + 8 * DIM;
                *(float2*)(C + o1) = make_float2(acc[mt][ng][0], acc[mt][ng][1]);
                *(float2*)(C + o2) = make_float2(acc[mt][ng][2], acc[mt][ng][3]);
            }
        }
    }
}

// ---------------------------------------------------------------------------
// HMMA flash-attention (R11-proven math): 128 Q-rows/CTA, chunked, occ 2.
// bOff shifts the BATCH origin so the grid splits into batch-halves whose
// flat-row ranges are contiguous (half A: rows [0,8192), half B: [8192,16384)).
// ---------------------------------------------------------------------------
#define AP 144
#define OFF_QH 0
#define OFF_QL 18432
#define OFF_KA 36864
#define OFF_KB 55296
#define OFF_VA 73728
#define OFF_VB 92160
#define OFF_MS 110592
#define ATTN_SMEM 111616
#define KHALF 9216

__global__ void __launch_bounds__(256, 2)
attn_hmma_kernel(const __nv_bfloat16* __restrict__ Qh, const __nv_bfloat16* __restrict__ Ql,
                 const __nv_bfloat16* __restrict__ Kh, const __nv_bfloat16* __restrict__ Kl,
                 const __nv_bfloat16* __restrict__ Vh, const __nv_bfloat16* __restrict__ Vl,
                 const int* __restrict__ maskp,
                 __nv_bfloat16* __restrict__ Oh, __nv_bfloat16* __restrict__ Ol, int bOff)
{
    extern __shared__ __align__(128) char smc[];
    const uint32_t sb = smem_u32(smc);
    int* Msm = (int*)(smc + OFF_MS);

    const int t = threadIdx.x, wid = t >> 5, lane = t & 31;
    const int b = bOff + (blockIdx.y >> 4), h = blockIdx.y & 15;
    const int n0 = blockIdx.x * 128;

    auto issueQ = [&]() {
        #pragma unroll
        for (int i = 0; i < 4; i++) {
            int idx = t + i * 256;
            int r = idx >> 3, ch = idx & 7;
            uint32_t doff = (uint32_t)(r * AP + ch * 16);
            size_t src = (size_t)(b * SEQ_N + n0 + r) * DIM + h * HD + ch * 8;
            CP_ASYNC16(sb + OFF_QH + doff, Qh + src);
            CP_ASYNC16(sb + OFF_QL + doff, Ql + src);
        }
        CP_COMMIT();
    };
    auto issueK = [&](int c, uint32_t off) {
        #pragma unroll
        for (int i = 0; i < 2; i++) {
            int idx = t + i * 256;
            int r = idx >> 3, ch = idx & 7;
            uint32_t doff = (uint32_t)(r * AP + ch * 16);
            size_t src = (size_t)(b * SEQ_M + c * 64 + r) * DIM + h * HD + ch * 8;
            CP_ASYNC16(sb + off + doff,         Kh + src);
            CP_ASYNC16(sb + off + KHALF + doff, Kl + src);
        }
        CP_COMMIT();
    };
    auto issueV = [&](int c, uint32_t off) {
        #pragma unroll
        for (int i = 0; i < 2; i++) {
            int idx = t + i * 256;
            int r = idx >> 3, ch = idx & 7;
            uint32_t doff = (uint32_t)(r * AP + ch * 16);
            size_t src = (size_t)(b * SEQ_M + c * 64 + r) * DIM + h * HD + ch * 8;
            CP_ASYNC16(sb + off + doff,         Vh + src);
            CP_ASYNC16(sb + off + KHALF + doff, Vl + src);
        }
        CP_COMMIT();
    };

    issueQ();
    issueK(0, OFF_KA); issueV(0, OFF_VA);
    issueK(1, OFF_KB); issueV(1, OFF_VB);
    Msm[t] = maskp[b * SEQ_M + t];

    const int wm = wid;
    const int g = lane >> 3, lrw = lane & 7;
    const uint32_t a_off = (uint32_t)(((g & 1) * 8 + lrw) * AP + (g >> 1) * 16);
    const uint32_t b_off = (uint32_t)(((g >> 1) * 8 + lrw) * AP + (g & 1) * 16);

    float o[8][4];
    #pragma unroll
    for (int j = 0; j < 8; j++)
        #pragma unroll
        for (int q = 0; q < 4; q++) o[j][q] = 0.0f;
    float M1 = -INFINITY, M2 = -INFINITY, S1 = 0.0f, S2 = 0.0f;
    float acc[8][4];
    const float scale = 0.125f;

    auto computeS = [&](uint32_t ko) {
        #pragma unroll
        for (int j = 0; j < 8; j++)
            #pragma unroll
            for (int q = 0; q < 4; q++) acc[j][q] = 0.0f;
        #pragma unroll
        for (int ks = 0; ks < 4; ks++) {
            const uint32_t kb = (uint32_t)(ks * 32);
            uint32_t fAh[4], fAl[4];
            LDM_X4(fAh[0], fAh[1], fAh[2], fAh[3],
                   sb + OFF_QH + (uint32_t)(wm * 16) * AP + kb + a_off);
            LDM_X4(fAl[0], fAl[1], fAl[2], fAl[3],
                   sb + OFF_QL + (uint32_t)(wm * 16) * AP + kb + a_off);
            #pragma unroll
            for (int nt = 0; nt < 4; nt++) {
                uint32_t krow = (uint32_t)(nt * 16) * AP + kb + b_off;
                uint32_t h0, h1, h2, h3, l0, l1, l2, l3;
                LDM_X4(h0, h1, h2, h3, sb + ko + krow);
                LDM_X4(l0, l1, l2, l3, sb + ko + KHALF + krow);
                uint32_t bh0[2] = {h0, h1}, bh1[2] = {h2, h3};
                uint32_t bl0[2] = {l0, l1}, bl1[2] = {l2, l3};
                MMA_BF16(acc[nt * 2],     fAh, bh0);
                MMA_BF16(acc[nt * 2],     fAh, bl0);
                MMA_BF16(acc[nt * 2],     fAl, bh0);
                MMA_BF16(acc[nt * 2 + 1], fAh, bh1);
                MMA_BF16(acc[nt * 2 + 1], fAh, bl1);
                MMA_BF16(acc[nt * 2 + 1], fAl, bh1);
            }
        }
    };

    auto softmaxPV = [&](int ci, uint32_t vo) {
        float m1 = -INFINITY, m2 = -INFINITY;
        #pragma unroll
        for (int j = 0; j < 8; j++) {
            int cb = ci * 64 + j * 8 + (lane & 3) * 2;
            bool k0 = Msm[cb] != 0, k1 = Msm[cb + 1] != 0;
            acc[j][0] = k0 ? acc[j][0] * scale : -1e30f;
            acc[j][1] = k1 ? acc[j][1] * scale : -1e30f;
            acc[j][2] = k0 ? acc[j][2] * scale : -1e30f;
            acc[j][3] = k1 ? acc[j][3] * scale : -1e30f;
            m1 = fmaxf(m1, fmaxf(acc[j][0], acc[j][1]));
            m2 = fmaxf(m2, fmaxf(acc[j][2], acc[j][3]));
        }
        m1 = fmaxf(m1, __shfl_xor_sync(0xffffffffu, m1, 1));
        m1 = fmaxf(m1, __shfl_xor_sync(0xffffffffu, m1, 2));
        m2 = fmaxf(m2, __shfl_xor_sync(0xffffffffu, m2, 1));
        m2 = fmaxf(m2, __shfl_xor_sync(0xffffffffu, m2, 2));

        float M1n = fmaxf(M1, m1), M2n = fmaxf(M2, m2);
        float sc1 = __expf(M1 - M1n), sc2 = __expf(M2 - M2n);
        #pragma unroll
        for (int j = 0; j < 8; j++) {
            o[j][0] *= sc1; o[j][1] *= sc1;
            o[j][2] *= sc2; o[j][3] *= sc2;
        }
        S1 *= sc1; S2 *= sc2;
        M1 = M1n; M2 = M2n;

        float s1 = 0.0f, s2 = 0.0f;
        #pragma unroll
        for (int j = 0; j < 8; j++) {
            acc[j][0] = __expf(acc[j][0] - M1);
            acc[j][1] = __expf(acc[j][1] - M1);
            acc[j][2] = __expf(acc[j][2] - M2);
            acc[j][3] = __expf(acc[j][3] - M2);
            s1 += acc[j][0] + acc[j][1];
            s2 += acc[j][2] + acc[j][3];
        }
        s1 += __shfl_xor_sync(0xffffffffu, s1, 1);
        s1 += __shfl_xor_sync(0xffffffffu, s1, 2);
        s2 += __shfl_xor_sync(0xffffffffu, s2, 1);
        s2 += __shfl_xor_sync(0xffffffffu, s2, 2);
        S1 += s1; S2 += s2;

        #pragma unroll
        for (int kk = 0; kk < 4; kk++) {
            const int j0 = kk * 2, j1 = j0 + 1;
            uint32_t ph[4], pl[4];
            split2(acc[j0][0], acc[j0][1], ph[0], pl[0]);
            split2(acc[j0][2], acc[j0][3], ph[1], pl[1]);
            split2(acc[j1][0], acc[j1][1], ph[2], pl[2]);
            split2(acc[j1][2], acc[j1][3], ph[3], pl[3]);

            const uint32_t vrow = (uint32_t)(kk * 16 + (g & 1) * 8 + lrw) * AP;
            #pragma unroll
            for (int ngp = 0; ngp < 4; ngp++) {
                const uint32_t vcol = (uint32_t)(((g >> 1) * 8 + ngp * 16) * 2);
                uint32_t h0, h1, h2, h3, l0, l1, l2, l3;
                LDM_X4T(h0, h1, h2, h3, sb + vo + vrow + vcol);
                LDM_X4T(l0, l1, l2, l3, sb + vo + KHALF + vrow + vcol);
                uint32_t vh0[2] = {h0, h1}, vh1[2] = {h2, h3};
                uint32_t vl0[2] = {l0, l1}, vl1[2] = {l2, l3};
                MMA_BF16(o[ngp * 2],     ph, vh0);
                MMA_BF16(o[ngp * 2],     ph, vl0);
                MMA_BF16(o[ngp * 2],     pl, vh0);
                MMA_BF16(o[ngp * 2 + 1], ph, vh1);
                MMA_BF16(o[ngp * 2 + 1], ph, vl1);
                MMA_BF16(o[ngp * 2 + 1], pl, vh1);
            }
        }
    };

    CP_WAIT(3); __syncthreads();
    computeS(OFF_KA);
    __syncthreads(); issueK(2, OFF_KA);
    CP_WAIT(3); __syncthreads();
    softmaxPV(0, OFF_VA);
    __syncthreads(); issueV(2, OFF_VA);
    CP_WAIT(3); __syncthreads();
    computeS(OFF_KB);
    __syncthreads(); issueK(3, OFF_KB);
    CP_WAIT(3); __syncthreads();
    softmaxPV(1, OFF_VB);
    __syncthreads(); issueV(3, OFF_VB);
    CP_WAIT(3); __syncthreads();
    computeS(OFF_KA);
    __syncthreads();
    CP_WAIT(2); __syncthreads();
    softmaxPV(2, OFF_VA);
    __syncthreads();
    CP_WAIT(1); __syncthreads();
    computeS(OFF_KB);
    CP_WAIT(0); __syncthreads();
    softmaxPV(3, OFF_VB);

    const float inv1 = 1.0f / S1, inv2 = 1.0f / S2;
    const int r1 = wm * 16 + (lane >> 2), r2 = r1 + 8;
    #pragma unroll
    for (int j = 0; j < 8; j++) {
        int col = j * 8 + (lane & 3) * 2;
        size_t go1 = (size_t)(b * SEQ_N + n0 + r1) * DIM + h * HD + col;
        size_t go2 = (size_t)(b * SEQ_N + n0 + r2) * DIM + h * HD + col;
        uint32_t hh, ll;
        split2(o[j][0] * inv1, o[j][1] * inv1, hh, ll);
        *(uint32_t*)(Oh + go1) = hh; *(uint32_t*)(Ol + go1) = ll;
        split2(o[j][2] * inv2, o[j][3] * inv2, hh, ll);
        *(uint32_t*)(Oh + go2) = hh; *(uint32_t*)(Ol + go2) = ll;
    }
}

// ---------------------------------------------------------------------------
// Host launcher — split-M software pipeline across two streams.
// Halves are BATCH-aligned so every kernel's flat-row range for half A is
// exactly [0,8192) and half B is [8192,16384) (no cross-stream overlap).
//   main: split_x, QprojA, attnA(b0,b1), OprojA, OprojB
//   aux : Wq^T, KV chain, Wo^T, QprojB, attnB(b2,b3)
// ---------------------------------------------------------------------------
#define HROWS (ROWS_X / 2)          // 8192 = batches {0,1}
#define HB    (BATCH / 2)           // 2

extern "C" void kernel_launch(void* const* d_in, const int* in_sizes, int n_in,
                              void* d_out, int out_size)
{
    const float* x    = (const float*)d_in[0];
    const float* ctx  = (const float*)d_in[1];
    const int*   mask = (const int*)d_in[2];
    const float* Wq   = (const float*)d_in[3];
    const float* Wk   = (const float*)d_in[4];
    const float* Wv   = (const float*)d_in[5];
    const float* Wo   = (const float*)d_in[6];
    float*       out  = (float*)d_out;

    __nv_bfloat16 *Ahp, *Alp, *Chp, *Clp, *Bqh, *Bql, *Bhp, *Blp, *Boh, *Bol;
    __nv_bfloat16 *Qhp, *Qlp, *Khp, *Klp, *Vhp, *Vlp;
    cudaGetSymbolAddress((void**)&Ahp, g_Ah);
    cudaGetSymbolAddress((void**)&Alp, g_Al);
    cudaGetSymbolAddress((void**)&Chp, g_Ch);
    cudaGetSymbolAddress((void**)&Clp, g_Cl);
    cudaGetSymbolAddress((void**)&Bqh, g_Bqh);
    cudaGetSymbolAddress((void**)&Bql, g_Bql);
    cudaGetSymbolAddress((void**)&Bhp, g_Bh);
    cudaGetSymbolAddress((void**)&Blp, g_Bl);
    cudaGetSymbolAddress((void**)&Boh, g_Boh);
    cudaGetSymbolAddress((void**)&Bol, g_Bol);
    cudaGetSymbolAddress((void**)&Qhp, g_Qh);
    cudaGetSymbolAddress((void**)&Qlp, g_Ql);
    cudaGetSymbolAddress((void**)&Khp, g_Kh);
    cudaGetSymbolAddress((void**)&Klp, g_Kl);
    cudaGetSymbolAddress((void**)&Vhp, g_Vh);
    cudaGetSymbolAddress((void**)&Vlp, g_Vl);

    cudaFuncSetAttribute(gemm_hmma_kernel<0>, cudaFuncAttributeMaxDynamicSharedMemorySize, GEMM_SMEM);
    cudaFuncSetAttribute(gemm_hmma_kernel<1>, cudaFuncAttributeMaxDynamicSharedMemorySize, GEMM_SMEM);
    cudaFuncSetAttribute(attn_hmma_kernel, cudaFuncAttributeMaxDynamicSharedMemorySize, ATTN_SMEM);

    static cudaStream_t s_aux = nullptr;
    static cudaEvent_t ev_fork = nullptr, ev_wq = nullptr, ev_kv = nullptr,
                       ev_wo = nullptr, ev_x = nullptr, ev_ab = nullptr;
    if (s_aux == nullptr) {
        cudaStreamCreateWithFlags(&s_aux, cudaStreamNonBlocking);
        cudaEventCreateWithFlags(&ev_fork, cudaEventDisableTiming);
        cudaEventCreateWithFlags(&ev_wq,   cudaEventDisableTiming);
        cudaEventCreateWithFlags(&ev_kv,   cudaEventDisableTiming);
        cudaEventCreateWithFlags(&ev_wo,   cudaEventDisableTiming);
        cudaEventCreateWithFlags(&ev_x,    cudaEventDisableTiming);
        cudaEventCreateWithFlags(&ev_ab,   cudaEventDisableTiming);
    }

    const int n4x = ROWS_X * DIM / 4;
    const int n4c = ROWS_C * CTX_DIM / 4;
    dim3 tb32(32, 8);
    const dim3 gHalf(DIM / BN, HROWS / BM);          // (8, 64)
    const dim3 aHalf(SEQ_N / 128, HB * HEADS);       // (32, 32)

    cudaEventRecord(ev_fork, 0);
    cudaStreamWaitEvent(s_aux, ev_fork, 0);

    // ---- aux stream: weights + KV + second-half pipeline ----
    transpose_split_kernel<<<dim3(DIM / 32, DIM / 32), tb32, 0, s_aux>>>(Wq, Bqh, Bql, DIM, DIM);
    cudaEventRecord(ev_wq, s_aux);
    split_kernel<<<n4c / 256, 256, 0, s_aux>>>(ctx, Chp, Clp, n4c);
    transpose_split_kernel<<<dim3(DIM / 32, CTX_DIM / 32), tb32, 0, s_aux>>>(Wk, Bhp, Blp, CTX_DIM, DIM);
    transpose_split_kernel<<<dim3(DIM / 32, CTX_DIM / 32), tb32, 0, s_aux>>>(
        Wv, Bhp + 1024 * CTX_DIM, Blp + 1024 * CTX_DIM, CTX_DIM, DIM);
    gemm_hmma_kernel<1><<<dim3(2048 / BN, ROWS_C / BM), 256, GEMM_SMEM, s_aux>>>(
        Chp, Clp, Bhp, Blp, nullptr, Khp, Klp, Vhp, Vlp, CTX_DIM, 0);
    cudaEventRecord(ev_kv, s_aux);
    transpose_split_kernel<<<dim3(DIM / 32, DIM / 32), tb32, 0, s_aux>>>(Wo, Boh, Bol, DIM, DIM);
    cudaEventRecord(ev_wo, s_aux);

    // ---- main stream: split x, first-half pipeline ----
    split_kernel<<<n4x / 256, 256>>>(x, Ahp, Alp, n4x);
    cudaEventRecord(ev_x, 0);
    cudaStreamWaitEvent(0, ev_wq, 0);
    gemm_hmma_kernel<1><<<gHalf, 256, GEMM_SMEM>>>(
        Ahp, Alp, Bqh, Bql, nullptr, Qhp, Qlp, nullptr, nullptr, DIM, 0);

    // aux: second-half Q projection (rows [8192,16384); needs split_x)
    cudaStreamWaitEvent(s_aux, ev_x, 0);
    gemm_hmma_kernel<1><<<gHalf, 256, GEMM_SMEM, s_aux>>>(
        Ahp, Alp, Bqh, Bql, nullptr, Qhp, Qlp, nullptr, nullptr, DIM, HROWS);

    // main: attention batches {0,1} -> writes Ah rows [0,8192) only
    cudaStreamWaitEvent(0, ev_kv, 0);
    attn_hmma_kernel<<<aHalf, 256, ATTN_SMEM>>>(
        Qhp, Qlp, Khp, Klp, Vhp, Vlp, mask, Ahp, Alp, 0);

    // aux: attention batches {2,3} -> writes Ah rows [8192,16384) after QprojB
    attn_hmma_kernel<<<aHalf, 256, ATTN_SMEM, s_aux>>>(
        Qhp, Qlp, Khp, Klp, Vhp, Vlp, mask, Ahp, Alp, HB);
    cudaEventRecord(ev_ab, s_aux);

    // main: O projections (first half after attnA; second half after attnB)
    cudaStreamWaitEvent(0, ev_wo, 0);
    gemm_hmma_kernel<0><<<gHalf, 256, GEMM_SMEM>>>(
        Ahp, Alp, Boh, Bol, out, nullptr, nullptr, nullptr, nullptr, DIM, 0);
    cudaStreamWaitEvent(0, ev_ab, 0);
    gemm_hmma_kernel<0><<<gHalf, 256, GEMM_SMEM>>>(
        Ahp, Alp, Boh, Bol, out, nullptr, nullptr, nullptr, nullptr, DIM, HROWS);
}

// round 16
// speedup vs baseline: 1.0316x; 1.0316x over previous
#include <cuda_runtime.h>
#include <cuda_bf16.h>
#include <math.h>
#include <stdint.h>

// Problem constants
#define BATCH 4
#define SEQ_N 4096
#define SEQ_M 256
#define DIM 1024
#define CTX_DIM 768
#define HEADS 16
#define HD 64
#define ROWS_X (BATCH * SEQ_N)      // 16384
#define ROWS_C (BATCH * SEQ_M)      // 1024

// Scratch (device globals)
__device__ __nv_bfloat16 g_Ah[ROWS_X * DIM];
__device__ __nv_bfloat16 g_Al[ROWS_X * DIM];
__device__ __nv_bfloat16 g_Ch[ROWS_C * CTX_DIM];
__device__ __nv_bfloat16 g_Cl[ROWS_C * CTX_DIM];
__device__ __nv_bfloat16 g_Bqh[DIM * DIM];      // Wq^T
__device__ __nv_bfloat16 g_Bql[DIM * DIM];
__device__ __nv_bfloat16 g_Bh[2048 * 1024];     // [Wk^T ; Wv^T]
__device__ __nv_bfloat16 g_Bl[2048 * 1024];
__device__ __nv_bfloat16 g_Boh[DIM * DIM];      // Wo^T
__device__ __nv_bfloat16 g_Bol[DIM * DIM];
__device__ __nv_bfloat16 g_Qh[ROWS_X * DIM];
__device__ __nv_bfloat16 g_Ql[ROWS_X * DIM];
__device__ __nv_bfloat16 g_Kh[ROWS_C * DIM];
__device__ __nv_bfloat16 g_Kl[ROWS_C * DIM];
__device__ __nv_bfloat16 g_Vh[ROWS_C * DIM];
__device__ __nv_bfloat16 g_Vl[ROWS_C * DIM];

// ---------------------------------------------------------------------------
// PTX helpers (sm_80+ portable)
// ---------------------------------------------------------------------------
__device__ __forceinline__ uint32_t smem_u32(const void* p) {
    uint32_t a;
    asm("{ .reg .u64 t; cvta.to.shared.u64 t, %1; cvt.u32.u64 %0, t; }" : "=r"(a) : "l"(p));
    return a;
}
#define CP_ASYNC16(dst, src) \
    asm volatile("cp.async.cg.shared.global [%0], [%1], 16;" :: "r"(dst), "l"(src))
#define CP_COMMIT() asm volatile("cp.async.commit_group;" ::: "memory")
#define CP_WAIT(n)  asm volatile("cp.async.wait_group %0;" :: "n"(n) : "memory")

#define LDM_X4(r0, r1, r2, r3, a) \
    asm volatile("ldmatrix.sync.aligned.m8n8.x4.shared.b16 {%0,%1,%2,%3}, [%4];" \
                 : "=r"(r0), "=r"(r1), "=r"(r2), "=r"(r3) : "r"(a))
#define LDM_X4T(r0, r1, r2, r3, a) \
    asm volatile("ldmatrix.sync.aligned.m8n8.x4.trans.shared.b16 {%0,%1,%2,%3}, [%4];" \
                 : "=r"(r0), "=r"(r1), "=r"(r2), "=r"(r3) : "r"(a))

#define MMA_BF16(d, a, b) \
    asm volatile("mma.sync.aligned.m16n8k16.row.col.f32.bf16.bf16.f32 " \
                 "{%0,%1,%2,%3},{%4,%5,%6,%7},{%8,%9},{%0,%1,%2,%3};" \
                 : "+f"((d)[0]), "+f"((d)[1]), "+f"((d)[2]), "+f"((d)[3]) \
                 : "r"((a)[0]), "r"((a)[1]), "r"((a)[2]), "r"((a)[3]), \
                   "r"((b)[0]), "r"((b)[1]))

__device__ __forceinline__ void split2(float x, float y, uint32_t& h, uint32_t& l) {
    __nv_bfloat162 hb = __float22bfloat162_rn(make_float2(x, y));
    float2 hf = __bfloat1622float2(hb);
    __nv_bfloat162 lb = __float22bfloat162_rn(make_float2(x - hf.x, y - hf.y));
    h = *(uint32_t*)&hb;
    l = *(uint32_t*)&lb;
}

// ---------------------------------------------------------------------------
// fp32 -> bf16 hi/lo split
// ---------------------------------------------------------------------------
__global__ void split_kernel(const float* __restrict__ X, __nv_bfloat16* __restrict__ Xh,
                             __nv_bfloat16* __restrict__ Xl, int n4)
{
    int i = blockIdx.x * blockDim.x + threadIdx.x;
    if (i >= n4) return;
    float4 v = ((const float4*)X)[i];
    float a[4] = {v.x, v.y, v.z, v.w};
    __nv_bfloat16 h[4], l[4];
    #pragma unroll
    for (int j = 0; j < 4; j++) {
        h[j] = __float2bfloat16(a[j]);
        l[j] = __float2bfloat16(a[j] - __bfloat162float(h[j]));
    }
    __nv_bfloat162* Hp = (__nv_bfloat162*)(Xh + 4 * (size_t)i);
    __nv_bfloat162* Lp = (__nv_bfloat162*)(Xl + 4 * (size_t)i);
    Hp[0] = __nv_bfloat162(h[0], h[1]); Hp[1] = __nv_bfloat162(h[2], h[3]);
    Lp[0] = __nv_bfloat162(l[0], l[1]); Lp[1] = __nv_bfloat162(l[2], l[3]);
}

// ---------------------------------------------------------------------------
// W[K][N] -> Th/Tl[N][K] bf16 hi/lo (transpose + split)
// ---------------------------------------------------------------------------
__global__ void transpose_split_kernel(const float* __restrict__ W, __nv_bfloat16* __restrict__ Th,
                                       __nv_bfloat16* __restrict__ Tl, int K, int N)
{
    __shared__ float tile[32][33];
    int n0 = blockIdx.x * 32, k0 = blockIdx.y * 32;
    int tx = threadIdx.x, ty = threadIdx.y;
    #pragma unroll
    for (int j = ty; j < 32; j += 8)
        tile[j][tx] = W[(size_t)(k0 + j) * N + n0 + tx];
    __syncthreads();
    #pragma unroll
    for (int j = ty; j < 32; j += 8) {
        float v = tile[tx][j];
        __nv_bfloat16 h = __float2bfloat16(v);
        __nv_bfloat16 l = __float2bfloat16(v - __bfloat162float(h));
        size_t o = (size_t)(n0 + j) * K + k0 + tx;
        Th[o] = h; Tl[o] = l;
    }
}

// ---------------------------------------------------------------------------
// HMMA bf16-split GEMM (R10-proven): 128x128x32 CTA tile, 8 warps of 64x32,
// 2-stage cp.async double buffer, 2 CTAs/SM. SPLIT=0: fp32 out. SPLIT=1:
// bf16 hi/lo out; cols >= 1024 routed to D pair (fused K|V projection).
// ---------------------------------------------------------------------------
#define BM 128
#define BN 128
#define BK 32
#define PITCH 80
#define TILE_B (128 * PITCH)
#define STAGE  (4 * TILE_B)
#define GEMM_SMEM (2 * STAGE)

template<int SPLIT>
__global__ void __launch_bounds__(256, 2)
gemm_hmma_kernel(const __nv_bfloat16* __restrict__ Ah, const __nv_bfloat16* __restrict__ Al,
                 const __nv_bfloat16* __restrict__ Bh, const __nv_bfloat16* __restrict__ Bl,
                 float* __restrict__ C, __nv_bfloat16* __restrict__ Ch,
                 __nv_bfloat16* __restrict__ Cl, __nv_bfloat16* __restrict__ Dh,
                 __nv_bfloat16* __restrict__ Dl, int K)
{
    extern __shared__ __align__(128) char sm[];
    const uint32_t sb = smem_u32(sm);
    const int t = threadIdx.x, wid = t >> 5, lane = t & 31;
    const int m0 = blockIdx.y * BM, n0 = blockIdx.x * BN;
    const int NC = K / BK;
    const int wr = wid & 1, wc = wid >> 1;

    const int lr0 = t >> 2;
    const int lch = t & 3;

    const int g = lane >> 3, lrw = lane & 7;
    const uint32_t a_off = (uint32_t)(((g & 1) * 8 + lrw) * PITCH + (g >> 1) * 16);
    const uint32_t b_off = (uint32_t)(((g >> 1) * 8 + lrw) * PITCH + (g & 1) * 16);

    float acc[4][4][4];
    #pragma unroll
    for (int mt = 0; mt < 4; mt++)
        #pragma unroll
        for (int ng = 0; ng < 4; ng++)
            #pragma unroll
            for (int q = 0; q < 4; q++) acc[mt][ng][q] = 0.0f;

    auto issue = [&](int c) {
        const int buf = c & 1;
        const uint32_t stg = sb + buf * STAGE;
        const int kt = c * BK;
        #pragma unroll
        for (int i = 0; i < 2; i++) {
            const int r = lr0 + i * 64;
            const uint32_t doff = (uint32_t)(r * PITCH + lch * 16);
            const size_t sa = (size_t)(m0 + r) * K + kt + lch * 8;
            const size_t sbi = (size_t)(n0 + r) * K + kt + lch * 8;
            CP_ASYNC16(stg + doff,               Ah + sa);
            CP_ASYNC16(stg + TILE_B + doff,      Al + sa);
            CP_ASYNC16(stg + 2 * TILE_B + doff,  Bh + sbi);
            CP_ASYNC16(stg + 3 * TILE_B + doff,  Bl + sbi);
        }
        CP_COMMIT();
    };

    issue(0);

    for (int c = 0; c < NC; c++) {
        if (c + 1 < NC) { issue(c + 1); CP_WAIT(1); }
        else            { CP_WAIT(0); }
        __syncthreads();

        const uint32_t stg = sb + (c & 1) * STAGE;
        const uint32_t aH = stg + (uint32_t)(wr * 64) * PITCH;
        const uint32_t aL = aH + TILE_B;
        const uint32_t bH = stg + 2 * TILE_B + (uint32_t)(wc * 32) * PITCH;
        const uint32_t bL = bH + TILE_B;

        #pragma unroll
        for (int ks = 0; ks < 2; ks++) {
            const uint32_t kb = (uint32_t)(ks * 32);
            uint32_t fAh[4][4], fAl[4][4], fBh[4][2], fBl[4][2];
            #pragma unroll
            for (int mt = 0; mt < 4; mt++) {
                uint32_t ad = aH + (uint32_t)(mt * 16) * PITCH + kb + a_off;
                LDM_X4(fAh[mt][0], fAh[mt][1], fAh[mt][2], fAh[mt][3], ad);
                uint32_t ad2 = aL + (uint32_t)(mt * 16) * PITCH + kb + a_off;
                LDM_X4(fAl[mt][0], fAl[mt][1], fAl[mt][2], fAl[mt][3], ad2);
            }
            #pragma unroll
            for (int nt = 0; nt < 2; nt++) {
                uint32_t bd = bH + (uint32_t)(nt * 16) * PITCH + kb + b_off;
                uint32_t r0, r1, r2, r3;
                LDM_X4(r0, r1, r2, r3, bd);
                fBh[nt * 2][0] = r0; fBh[nt * 2][1] = r1;
                fBh[nt * 2 + 1][0] = r2; fBh[nt * 2 + 1][1] = r3;
                uint32_t bd2 = bL + (uint32_t)(nt * 16) * PITCH + kb + b_off;
                LDM_X4(r0, r1, r2, r3, bd2);
                fBl[nt * 2][0] = r0; fBl[nt * 2][1] = r1;
                fBl[nt * 2 + 1][0] = r2; fBl[nt * 2 + 1][1] = r3;
            }
            #pragma unroll
            for (int mt = 0; mt < 4; mt++) {
                #pragma unroll
                for (int ng = 0; ng < 4; ng++) {
                    MMA_BF16(acc[mt][ng], fAh[mt], fBh[ng]);
                    MMA_BF16(acc[mt][ng], fAh[mt], fBl[ng]);
                    MMA_BF16(acc[mt][ng], fAl[mt], fBh[ng]);
                }
            }
        }
        __syncthreads();
    }

    const int row0 = m0 + wr * 64 + lane / 4;
    const int col0 = wc * 32 + (lane % 4) * 2;
    #pragma unroll
    for (int mt = 0; mt < 4; mt++) {
        #pragma unroll
        for (int ng = 0; ng < 4; ng++) {
            int gc = n0 + col0 + ng * 8;
            if (SPLIT) {
                __nv_bfloat16 *Hp, *Lp;
                if (gc < 1024) { Hp = Ch; Lp = Cl; }
                else           { Hp = Dh; Lp = Dl; gc -= 1024; }
                size_t o1 = (size_t)(row0 + mt * 16) * DIM + gc;
                size_t o2 = o1 + 8 * DIM;
                uint32_t h, l;
                split2(acc[mt][ng][0], acc[mt][ng][1], h, l);
                *(uint32_t*)(Hp + o1) = h; *(uint32_t*)(Lp + o1) = l;
                split2(acc[mt][ng][2], acc[mt][ng][3], h, l);
                *(uint32_t*)(Hp + o2) = h; *(uint32_t*)(Lp + o2) = l;
            } else {
                size_t o1 = (size_t)(row0 + mt * 16) * DIM + gc;
                size_t o2 = o1 + 8 * DIM;
                *(float2*)(C + o1) = make_float2(acc[mt][ng][0], acc[mt][ng][1]);
                *(float2*)(C + o2) = make_float2(acc[mt][ng][2], acc[mt][ng][3]);
            }
        }
    }
}

// ---------------------------------------------------------------------------
// HMMA flash-attention (R12 math, full 3-MMA PV): 128 Q-rows/CTA, chunked
// occ-2 online softmax pipeline. Micro-opts vs R12:
//  - Q fragments loaded ONCE into registers (not re-ldmatrix'd per chunk)
//  - softmax in log2 domain: scale*log2e folded into masking mul, exp2f used
// ---------------------------------------------------------------------------
#define AP 144
#define OFF_QH 0
#define OFF_QL 18432
#define OFF_KA 36864
#define OFF_KB 55296
#define OFF_VA 73728
#define OFF_VB 92160
#define OFF_MS 110592
#define ATTN_SMEM 111616
#define KHALF 9216

__global__ void __launch_bounds__(256, 2)
attn_hmma_kernel(const __nv_bfloat16* __restrict__ Qh, const __nv_bfloat16* __restrict__ Ql,
                 const __nv_bfloat16* __restrict__ Kh, const __nv_bfloat16* __restrict__ Kl,
                 const __nv_bfloat16* __restrict__ Vh, const __nv_bfloat16* __restrict__ Vl,
                 const int* __restrict__ maskp,
                 __nv_bfloat16* __restrict__ Oh, __nv_bfloat16* __restrict__ Ol)
{
    extern __shared__ __align__(128) char smc[];
    const uint32_t sb = smem_u32(smc);
    int* Msm = (int*)(smc + OFF_MS);

    const int t = threadIdx.x, wid = t >> 5, lane = t & 31;
    const int b = blockIdx.y >> 4, h = blockIdx.y & 15;
    const int n0 = blockIdx.x * 128;

    auto issueQ = [&]() {
        #pragma unroll
        for (int i = 0; i < 4; i++) {
            int idx = t + i * 256;
            int r = idx >> 3, ch = idx & 7;
            uint32_t doff = (uint32_t)(r * AP + ch * 16);
            size_t src = (size_t)(b * SEQ_N + n0 + r) * DIM + h * HD + ch * 8;
            CP_ASYNC16(sb + OFF_QH + doff, Qh + src);
            CP_ASYNC16(sb + OFF_QL + doff, Ql + src);
        }
        CP_COMMIT();
    };
    auto issueK = [&](int c, uint32_t off) {
        #pragma unroll
        for (int i = 0; i < 2; i++) {
            int idx = t + i * 256;
            int r = idx >> 3, ch = idx & 7;
            uint32_t doff = (uint32_t)(r * AP + ch * 16);
            size_t src = (size_t)(b * SEQ_M + c * 64 + r) * DIM + h * HD + ch * 8;
            CP_ASYNC16(sb + off + doff,         Kh + src);
            CP_ASYNC16(sb + off + KHALF + doff, Kl + src);
        }
        CP_COMMIT();
    };
    auto issueV = [&](int c, uint32_t off) {
        #pragma unroll
        for (int i = 0; i < 2; i++) {
            int idx = t + i * 256;
            int r = idx >> 3, ch = idx & 7;
            uint32_t doff = (uint32_t)(r * AP + ch * 16);
            size_t src = (size_t)(b * SEQ_M + c * 64 + r) * DIM + h * HD + ch * 8;
            CP_ASYNC16(sb + off + doff,         Vh + src);
            CP_ASYNC16(sb + off + KHALF + doff, Vl + src);
        }
        CP_COMMIT();
    };

    issueQ();
    issueK(0, OFF_KA); issueV(0, OFF_VA);
    issueK(1, OFF_KB); issueV(1, OFF_VB);
    Msm[t] = maskp[b * SEQ_M + t];

    const int wm = wid;
    const int g = lane >> 3, lrw = lane & 7;
    const uint32_t a_off = (uint32_t)(((g & 1) * 8 + lrw) * AP + (g >> 1) * 16);
    const uint32_t b_off = (uint32_t)(((g >> 1) * 8 + lrw) * AP + (g & 1) * 16);

    float o[8][4];
    #pragma unroll
    for (int j = 0; j < 8; j++)
        #pragma unroll
        for (int q = 0; q < 4; q++) o[j][q] = 0.0f;
    float M1 = -INFINITY, M2 = -INFINITY, S1 = 0.0f, S2 = 0.0f;
    float acc[8][4];
    uint32_t qh_f[4][4], ql_f[4][4];      // Q fragments, loaded once
    // scale * log2(e): softmax runs in the exp2 domain
    const float scl2 = 0.125f * 1.4426950408889634f;

    auto computeS = [&](uint32_t ko) {
        #pragma unroll
        for (int j = 0; j < 8; j++)
            #pragma unroll
            for (int q = 0; q < 4; q++) acc[j][q] = 0.0f;
        #pragma unroll
        for (int ks = 0; ks < 4; ks++) {
            const uint32_t kb = (uint32_t)(ks * 32);
            #pragma unroll
            for (int nt = 0; nt < 4; nt++) {
                uint32_t krow = (uint32_t)(nt * 16) * AP + kb + b_off;
                uint32_t h0, h1, h2, h3, l0, l1, l2, l3;
                LDM_X4(h0, h1, h2, h3, sb + ko + krow);
                LDM_X4(l0, l1, l2, l3, sb + ko + KHALF + krow);
                uint32_t bh0[2] = {h0, h1}, bh1[2] = {h2, h3};
                uint32_t bl0[2] = {l0, l1}, bl1[2] = {l2, l3};
                MMA_BF16(acc[nt * 2],     qh_f[ks], bh0);
                MMA_BF16(acc[nt * 2],     qh_f[ks], bl0);
                MMA_BF16(acc[nt * 2],     ql_f[ks], bh0);
                MMA_BF16(acc[nt * 2 + 1], qh_f[ks], bh1);
                MMA_BF16(acc[nt * 2 + 1], qh_f[ks], bl1);
                MMA_BF16(acc[nt * 2 + 1], ql_f[ks], bh1);
            }
        }
    };

    auto softmaxPV = [&](int ci, uint32_t vo) {
        float m1 = -INFINITY, m2 = -INFINITY;
        #pragma unroll
        for (int j = 0; j < 8; j++) {
            int cb = ci * 64 + j * 8 + (lane & 3) * 2;
            bool k0 = Msm[cb] != 0, k1 = Msm[cb + 1] != 0;
            acc[j][0] = k0 ? acc[j][0] * scl2 : -1e30f;
            acc[j][1] = k1 ? acc[j][1] * scl2 : -1e30f;
            acc[j][2] = k0 ? acc[j][2] * scl2 : -1e30f;
            acc[j][3] = k1 ? acc[j][3] * scl2 : -1e30f;
            m1 = fmaxf(m1, fmaxf(acc[j][0], acc[j][1]));
            m2 = fmaxf(m2, fmaxf(acc[j][2], acc[j][3]));
        }
        m1 = fmaxf(m1, __shfl_xor_sync(0xffffffffu, m1, 1));
        m1 = fmaxf(m1, __shfl_xor_sync(0xffffffffu, m1, 2));
        m2 = fmaxf(m2, __shfl_xor_sync(0xffffffffu, m2, 1));
        m2 = fmaxf(m2, __shfl_xor_sync(0xffffffffu, m2, 2));

        float M1n = fmaxf(M1, m1), M2n = fmaxf(M2, m2);
        float sc1 = exp2f(M1 - M1n), sc2 = exp2f(M2 - M2n);
        #pragma unroll
        for (int j = 0; j < 8; j++) {
            o[j][0] *= sc1; o[j][1] *= sc1;
            o[j][2] *= sc2; o[j][3] *= sc2;
        }
        S1 *= sc1; S2 *= sc2;
        M1 = M1n; M2 = M2n;

        float s1 = 0.0f, s2 = 0.0f;
        #pragma unroll
        for (int j = 0; j < 8; j++) {
            acc[j][0] = exp2f(acc[j][0] - M1);
            acc[j][1] = exp2f(acc[j][1] - M1);
            acc[j][2] = exp2f(acc[j][2] - M2);
            acc[j][3] = exp2f(acc[j][3] - M2);
            s1 += acc[j][0] + acc[j][1];
            s2 += acc[j][2] + acc[j][3];
        }
        s1 += __shfl_xor_sync(0xffffffffu, s1, 1);
        s1 += __shfl_xor_sync(0xffffffffu, s1, 2);
        s2 += __shfl_xor_sync(0xffffffffu, s2, 1);
        s2 += __shfl_xor_sync(0xffffffffu, s2, 2);
        S1 += s1; S2 += s2;

        #pragma unroll
        for (int kk = 0; kk < 4; kk++) {
            const int j0 = kk * 2, j1 = j0 + 1;
            uint32_t ph[4], pl[4];
            split2(acc[j0][0], acc[j0][1], ph[0], pl[0]);
            split2(acc[j0][2], acc[j0][3], ph[1], pl[1]);
            split2(acc[j1][0], acc[j1][1], ph[2], pl[2]);
            split2(acc[j1][2], acc[j1][3], ph[3], pl[3]);

            const uint32_t vrow = (uint32_t)(kk * 16 + (g & 1) * 8 + lrw) * AP;
            #pragma unroll
            for (int ngp = 0; ngp < 4; ngp++) {
                const uint32_t vcol = (uint32_t)(((g >> 1) * 8 + ngp * 16) * 2);
                uint32_t h0, h1, h2, h3, l0, l1, l2, l3;
                LDM_X4T(h0, h1, h2, h3, sb + vo + vrow + vcol);
                LDM_X4T(l0, l1, l2, l3, sb + vo + KHALF + vrow + vcol);
                uint32_t vh0[2] = {h0, h1}, vh1[2] = {h2, h3};
                uint32_t vl0[2] = {l0, l1}, vl1[2] = {l2, l3};
                MMA_BF16(o[ngp * 2],     ph, vh0);
                MMA_BF16(o[ngp * 2],     ph, vl0);
                MMA_BF16(o[ngp * 2],     pl, vh0);
                MMA_BF16(o[ngp * 2 + 1], ph, vh1);
                MMA_BF16(o[ngp * 2 + 1], ph, vl1);
                MMA_BF16(o[ngp * 2 + 1], pl, vh1);
            }
        }
    };

    // --- pipelined mainloop ---
    CP_WAIT(3); __syncthreads();          // Q, K0 ready
    // load Q fragments once
    #pragma unroll
    for (int ks = 0; ks < 4; ks++) {
        const uint32_t kb = (uint32_t)(ks * 32);
        LDM_X4(qh_f[ks][0], qh_f[ks][1], qh_f[ks][2], qh_f[ks][3],
               sb + OFF_QH + (uint32_t)(wm * 16) * AP + kb + a_off);
        LDM_X4(ql_f[ks][0], ql_f[ks][1], ql_f[ks][2], ql_f[ks][3],
               sb + OFF_QL + (uint32_t)(wm * 16) * AP + kb + a_off);
    }
    computeS(OFF_KA);
    __syncthreads(); issueK(2, OFF_KA);
    CP_WAIT(3); __syncthreads();          // V0 ready
    softmaxPV(0, OFF_VA);
    __syncthreads(); issueV(2, OFF_VA);
    CP_WAIT(3); __syncthreads();          // K1 ready
    computeS(OFF_KB);
    __syncthreads(); issueK(3, OFF_KB);
    CP_WAIT(3); __syncthreads();          // V1 ready
    softmaxPV(1, OFF_VB);
    __syncthreads(); issueV(3, OFF_VB);
    CP_WAIT(3); __syncthreads();          // K2 ready
    computeS(OFF_KA);
    __syncthreads();
    CP_WAIT(2); __syncthreads();          // V2 ready
    softmaxPV(2, OFF_VA);
    __syncthreads();
    CP_WAIT(1); __syncthreads();          // K3 ready
    computeS(OFF_KB);
    CP_WAIT(0); __syncthreads();          // V3 ready
    softmaxPV(3, OFF_VB);

    const float inv1 = 1.0f / S1, inv2 = 1.0f / S2;
    const int r1 = wm * 16 + (lane >> 2), r2 = r1 + 8;
    #pragma unroll
    for (int j = 0; j < 8; j++) {
        int col = j * 8 + (lane & 3) * 2;
        size_t go1 = (size_t)(b * SEQ_N + n0 + r1) * DIM + h * HD + col;
        size_t go2 = (size_t)(b * SEQ_N + n0 + r2) * DIM + h * HD + col;
        uint32_t hh, ll;
        split2(o[j][0] * inv1, o[j][1] * inv1, hh, ll);
        *(uint32_t*)(Oh + go1) = hh; *(uint32_t*)(Ol + go1) = ll;
        split2(o[j][2] * inv2, o[j][3] * inv2, hh, ll);
        *(uint32_t*)(Oh + go2) = hh; *(uint32_t*)(Ol + go2) = ll;
    }
}

// ---------------------------------------------------------------------------
// Host launcher — R12-proven two-stream fork/join schedule.
// ---------------------------------------------------------------------------
extern "C" void kernel_launch(void* const* d_in, const int* in_sizes, int n_in,
                              void* d_out, int out_size)
{
    const float* x    = (const float*)d_in[0];
    const float* ctx  = (const float*)d_in[1];
    const int*   mask = (const int*)d_in[2];
    const float* Wq   = (const float*)d_in[3];
    const float* Wk   = (const float*)d_in[4];
    const float* Wv   = (const float*)d_in[5];
    const float* Wo   = (const float*)d_in[6];
    float*       out  = (float*)d_out;

    __nv_bfloat16 *Ahp, *Alp, *Chp, *Clp, *Bqh, *Bql, *Bhp, *Blp, *Boh, *Bol;
    __nv_bfloat16 *Qhp, *Qlp, *Khp, *Klp, *Vhp, *Vlp;
    cudaGetSymbolAddress((void**)&Ahp, g_Ah);
    cudaGetSymbolAddress((void**)&Alp, g_Al);
    cudaGetSymbolAddress((void**)&Chp, g_Ch);
    cudaGetSymbolAddress((void**)&Clp, g_Cl);
    cudaGetSymbolAddress((void**)&Bqh, g_Bqh);
    cudaGetSymbolAddress((void**)&Bql, g_Bql);
    cudaGetSymbolAddress((void**)&Bhp, g_Bh);
    cudaGetSymbolAddress((void**)&Blp, g_Bl);
    cudaGetSymbolAddress((void**)&Boh, g_Boh);
    cudaGetSymbolAddress((void**)&Bol, g_Bol);
    cudaGetSymbolAddress((void**)&Qhp, g_Qh);
    cudaGetSymbolAddress((void**)&Qlp, g_Ql);
    cudaGetSymbolAddress((void**)&Khp, g_Kh);
    cudaGetSymbolAddress((void**)&Klp, g_Kl);
    cudaGetSymbolAddress((void**)&Vhp, g_Vh);
    cudaGetSymbolAddress((void**)&Vlp, g_Vl);

    cudaFuncSetAttribute(gemm_hmma_kernel<0>, cudaFuncAttributeMaxDynamicSharedMemorySize, GEMM_SMEM);
    cudaFuncSetAttribute(gemm_hmma_kernel<1>, cudaFuncAttributeMaxDynamicSharedMemorySize, GEMM_SMEM);
    cudaFuncSetAttribute(attn_hmma_kernel, cudaFuncAttributeMaxDynamicSharedMemorySize, ATTN_SMEM);

    static cudaStream_t s_aux = nullptr;
    static cudaEvent_t ev_fork = nullptr, ev_wq = nullptr, ev_kv = nullptr, ev_wo = nullptr;
    if (s_aux == nullptr) {
        cudaStreamCreateWithFlags(&s_aux, cudaStreamNonBlocking);
        cudaEventCreateWithFlags(&ev_fork, cudaEventDisableTiming);
        cudaEventCreateWithFlags(&ev_wq,   cudaEventDisableTiming);
        cudaEventCreateWithFlags(&ev_kv,   cudaEventDisableTiming);
        cudaEventCreateWithFlags(&ev_wo,   cudaEventDisableTiming);
    }

    const int n4x = ROWS_X * DIM / 4;
    const int n4c = ROWS_C * CTX_DIM / 4;
    dim3 tb32(32, 8);

    cudaEventRecord(ev_fork, 0);
    cudaStreamWaitEvent(s_aux, ev_fork, 0);

    // aux: Wq^T, KV chain, Wo^T
    transpose_split_kernel<<<dim3(DIM / 32, DIM / 32), tb32, 0, s_aux>>>(Wq, Bqh, Bql, DIM, DIM);
    cudaEventRecord(ev_wq, s_aux);
    split_kernel<<<n4c / 256, 256, 0, s_aux>>>(ctx, Chp, Clp, n4c);
    transpose_split_kernel<<<dim3(DIM / 32, CTX_DIM / 32), tb32, 0, s_aux>>>(Wk, Bhp, Blp, CTX_DIM, DIM);
    transpose_split_kernel<<<dim3(DIM / 32, CTX_DIM / 32), tb32, 0, s_aux>>>(
        Wv, Bhp + 1024 * CTX_DIM, Blp + 1024 * CTX_DIM, CTX_DIM, DIM);
    gemm_hmma_kernel<1><<<dim3(2048 / BN, ROWS_C / BM), 256, GEMM_SMEM, s_aux>>>(
        Chp, Clp, Bhp, Blp, nullptr, Khp, Klp, Vhp, Vlp, CTX_DIM);
    cudaEventRecord(ev_kv, s_aux);
    transpose_split_kernel<<<dim3(DIM / 32, DIM / 32), tb32, 0, s_aux>>>(Wo, Boh, Bol, DIM, DIM);
    cudaEventRecord(ev_wo, s_aux);

    // main: split x, Q projection, attention, O projection
    split_kernel<<<n4x / 256, 256>>>(x, Ahp, Alp, n4x);
    cudaStreamWaitEvent(0, ev_wq, 0);
    gemm_hmma_kernel<1><<<dim3(DIM / BN, ROWS_X / BM), 256, GEMM_SMEM>>>(
        Ahp, Alp, Bqh, Bql, nullptr, Qhp, Qlp, nullptr, nullptr, DIM);

    cudaStreamWaitEvent(0, ev_kv, 0);
    attn_hmma_kernel<<<dim3(SEQ_N / 128, BATCH * HEADS), 256, ATTN_SMEM>>>(
        Qhp, Qlp, Khp, Klp, Vhp, Vlp, mask, Ahp, Alp);

    cudaStreamWaitEvent(0, ev_wo, 0);
    gemm_hmma_kernel<0><<<dim3(DIM / BN, ROWS_X / BM), 256, GEMM_SMEM>>>(
        Ahp, Alp, Boh, Bol, out, nullptr, nullptr, nullptr, nullptr, DIM);
}

// round 17
// speedup vs baseline: 1.0787x; 1.0456x over previous
#include <cuda_runtime.h>
#include <cuda_fp16.h>
#include <math.h>
#include <stdint.h>

// Problem constants
#define BATCH 4
#define SEQ_N 4096
#define SEQ_M 256
#define DIM 1024
#define CTX_DIM 768
#define HEADS 16
#define HD 64
#define ROWS_X (BATCH * SEQ_N)      // 16384
#define ROWS_C (BATCH * SEQ_M)      // 1024

// Scratch (device globals) — fp16 hi/lo split everywhere
__device__ __half g_Ah[ROWS_X * DIM];
__device__ __half g_Al[ROWS_X * DIM];
__device__ __half g_Ch[ROWS_C * CTX_DIM];
__device__ __half g_Cl[ROWS_C * CTX_DIM];
__device__ __half g_Bqh[DIM * DIM];      // Wq^T
__device__ __half g_Bql[DIM * DIM];
__device__ __half g_Bh[2048 * 1024];     // [Wk^T ; Wv^T]
__device__ __half g_Bl[2048 * 1024];
__device__ __half g_Boh[DIM * DIM];      // Wo^T
__device__ __half g_Bol[DIM * DIM];
__device__ __half g_Qh[ROWS_X * DIM];
__device__ __half g_Ql[ROWS_X * DIM];
__device__ __half g_Kh[ROWS_C * DIM];
__device__ __half g_Kl[ROWS_C * DIM];
__device__ __half g_Vh[ROWS_C * DIM];

// ---------------------------------------------------------------------------
// PTX helpers (sm_80+ portable)
// ---------------------------------------------------------------------------
__device__ __forceinline__ uint32_t smem_u32(const void* p) {
    uint32_t a;
    asm("{ .reg .u64 t; cvta.to.shared.u64 t, %1; cvt.u32.u64 %0, t; }" : "=r"(a) : "l"(p));
    return a;
}
#define CP_ASYNC16(dst, src) \
    asm volatile("cp.async.cg.shared.global [%0], [%1], 16;" :: "r"(dst), "l"(src))
#define CP_COMMIT() asm volatile("cp.async.commit_group;" ::: "memory")
#define CP_WAIT(n)  asm volatile("cp.async.wait_group %0;" :: "n"(n) : "memory")

#define LDM_X4(r0, r1, r2, r3, a) \
    asm volatile("ldmatrix.sync.aligned.m8n8.x4.shared.b16 {%0,%1,%2,%3}, [%4];" \
                 : "=r"(r0), "=r"(r1), "=r"(r2), "=r"(r3) : "r"(a))
#define LDM_X4T(r0, r1, r2, r3, a) \
    asm volatile("ldmatrix.sync.aligned.m8n8.x4.trans.shared.b16 {%0,%1,%2,%3}, [%4];" \
                 : "=r"(r0), "=r"(r1), "=r"(r2), "=r"(r3) : "r"(a))

#define MMA_F16(d, a, b) \
    asm volatile("mma.sync.aligned.m16n8k16.row.col.f32.f16.f16.f32 " \
                 "{%0,%1,%2,%3},{%4,%5,%6,%7},{%8,%9},{%0,%1,%2,%3};" \
                 : "+f"((d)[0]), "+f"((d)[1]), "+f"((d)[2]), "+f"((d)[3]) \
                 : "r"((a)[0]), "r"((a)[1]), "r"((a)[2]), "r"((a)[3]), \
                   "r"((b)[0]), "r"((b)[1]))

__device__ __forceinline__ void split2h(float x, float y, uint32_t& h, uint32_t& l) {
    __half2 hb = __float22half2_rn(make_float2(x, y));
    float2 hf = __half22float2(hb);
    __half2 lb = __float22half2_rn(make_float2(x - hf.x, y - hf.y));
    h = *(uint32_t*)&hb;
    l = *(uint32_t*)&lb;
}
__device__ __forceinline__ uint32_t pack_h2(float x, float y) {
    __half2 hb = __float22half2_rn(make_float2(x, y));
    return *(uint32_t*)&hb;
}

// ---------------------------------------------------------------------------
// fp32 -> fp16 hi/lo split
// ---------------------------------------------------------------------------
__global__ void split_kernel(const float* __restrict__ X, __half* __restrict__ Xh,
                             __half* __restrict__ Xl, int n4)
{
    int i = blockIdx.x * blockDim.x + threadIdx.x;
    if (i >= n4) return;
    float4 v = ((const float4*)X)[i];
    float a[4] = {v.x, v.y, v.z, v.w};
    __half h[4], l[4];
    #pragma unroll
    for (int j = 0; j < 4; j++) {
        h[j] = __float2half(a[j]);
        l[j] = __float2half(a[j] - __half2float(h[j]));
    }
    __half2* Hp = (__half2*)(Xh + 4 * (size_t)i);
    __half2* Lp = (__half2*)(Xl + 4 * (size_t)i);
    Hp[0] = __half2(h[0], h[1]); Hp[1] = __half2(h[2], h[3]);
    Lp[0] = __half2(l[0], l[1]); Lp[1] = __half2(l[2], l[3]);
}

// ---------------------------------------------------------------------------
// W[K][N] -> Th/Tl[N][K] fp16 hi/lo (transpose + split)
// ---------------------------------------------------------------------------
__global__ void transpose_split_kernel(const float* __restrict__ W, __half* __restrict__ Th,
                                       __half* __restrict__ Tl, int K, int N)
{
    __shared__ float tile[32][33];
    int n0 = blockIdx.x * 32, k0 = blockIdx.y * 32;
    int tx = threadIdx.x, ty = threadIdx.y;
    #pragma unroll
    for (int j = ty; j < 32; j += 8)
        tile[j][tx] = W[(size_t)(k0 + j) * N + n0 + tx];
    __syncthreads();
    #pragma unroll
    for (int j = ty; j < 32; j += 8) {
        float v = tile[tx][j];
        __half h = __float2half(v);
        __half l = __float2half(v - __half2float(h));
        size_t o = (size_t)(n0 + j) * K + k0 + tx;
        Th[o] = h; Tl[o] = l;
    }
}

// ---------------------------------------------------------------------------
// HMMA fp16-split GEMM (R10 structure): 128x128x32, 8 warps of 64x32,
// 2-stage cp.async, 2 CTAs/SM. 3-MMA split retained (error ~1e-6).
// SPLIT=0: fp32 out. SPLIT=1: fp16 hi/lo out; cols>=1024 -> D (fused K|V).
// ---------------------------------------------------------------------------
#define BM 128
#define BN 128
#define BK 32
#define PITCH 80
#define TILE_B (128 * PITCH)
#define STAGE  (4 * TILE_B)
#define GEMM_SMEM (2 * STAGE)

template<int SPLIT>
__global__ void __launch_bounds__(256, 2)
gemm_hmma_kernel(const __half* __restrict__ Ah, const __half* __restrict__ Al,
                 const __half* __restrict__ Bh, const __half* __restrict__ Bl,
                 float* __restrict__ C, __half* __restrict__ Ch,
                 __half* __restrict__ Cl, __half* __restrict__ Dh,
                 __half* __restrict__ Dl, int K)
{
    extern __shared__ __align__(128) char sm[];
    const uint32_t sb = smem_u32(sm);
    const int t = threadIdx.x, wid = t >> 5, lane = t & 31;
    const int m0 = blockIdx.y * BM, n0 = blockIdx.x * BN;
    const int NC = K / BK;
    const int wr = wid & 1, wc = wid >> 1;

    const int lr0 = t >> 2;
    const int lch = t & 3;

    const int g = lane >> 3, lrw = lane & 7;
    const uint32_t a_off = (uint32_t)(((g & 1) * 8 + lrw) * PITCH + (g >> 1) * 16);
    const uint32_t b_off = (uint32_t)(((g >> 1) * 8 + lrw) * PITCH + (g & 1) * 16);

    float acc[4][4][4];
    #pragma unroll
    for (int mt = 0; mt < 4; mt++)
        #pragma unroll
        for (int ng = 0; ng < 4; ng++)
            #pragma unroll
            for (int q = 0; q < 4; q++) acc[mt][ng][q] = 0.0f;

    auto issue = [&](int c) {
        const int buf = c & 1;
        const uint32_t stg = sb + buf * STAGE;
        const int kt = c * BK;
        #pragma unroll
        for (int i = 0; i < 2; i++) {
            const int r = lr0 + i * 64;
            const uint32_t doff = (uint32_t)(r * PITCH + lch * 16);
            const size_t sa = (size_t)(m0 + r) * K + kt + lch * 8;
            const size_t sbi = (size_t)(n0 + r) * K + kt + lch * 8;
            CP_ASYNC16(stg + doff,               Ah + sa);
            CP_ASYNC16(stg + TILE_B + doff,      Al + sa);
            CP_ASYNC16(stg + 2 * TILE_B + doff,  Bh + sbi);
            CP_ASYNC16(stg + 3 * TILE_B + doff,  Bl + sbi);
        }
        CP_COMMIT();
    };

    issue(0);

    for (int c = 0; c < NC; c++) {
        if (c + 1 < NC) { issue(c + 1); CP_WAIT(1); }
        else            { CP_WAIT(0); }
        __syncthreads();

        const uint32_t stg = sb + (c & 1) * STAGE;
        const uint32_t aH = stg + (uint32_t)(wr * 64) * PITCH;
        const uint32_t aL = aH + TILE_B;
        const uint32_t bH = stg + 2 * TILE_B + (uint32_t)(wc * 32) * PITCH;
        const uint32_t bL = bH + TILE_B;

        #pragma unroll
        for (int ks = 0; ks < 2; ks++) {
            const uint32_t kb = (uint32_t)(ks * 32);
            uint32_t fAh[4][4], fAl[4][4], fBh[4][2], fBl[4][2];
            #pragma unroll
            for (int mt = 0; mt < 4; mt++) {
                uint32_t ad = aH + (uint32_t)(mt * 16) * PITCH + kb + a_off;
                LDM_X4(fAh[mt][0], fAh[mt][1], fAh[mt][2], fAh[mt][3], ad);
                uint32_t ad2 = aL + (uint32_t)(mt * 16) * PITCH + kb + a_off;
                LDM_X4(fAl[mt][0], fAl[mt][1], fAl[mt][2], fAl[mt][3], ad2);
            }
            #pragma unroll
            for (int nt = 0; nt < 2; nt++) {
                uint32_t bd = bH + (uint32_t)(nt * 16) * PITCH + kb + b_off;
                uint32_t r0, r1, r2, r3;
                LDM_X4(r0, r1, r2, r3, bd);
                fBh[nt * 2][0] = r0; fBh[nt * 2][1] = r1;
                fBh[nt * 2 + 1][0] = r2; fBh[nt * 2 + 1][1] = r3;
                uint32_t bd2 = bL + (uint32_t)(nt * 16) * PITCH + kb + b_off;
                LDM_X4(r0, r1, r2, r3, bd2);
                fBl[nt * 2][0] = r0; fBl[nt * 2][1] = r1;
                fBl[nt * 2 + 1][0] = r2; fBl[nt * 2 + 1][1] = r3;
            }
            #pragma unroll
            for (int mt = 0; mt < 4; mt++) {
                #pragma unroll
                for (int ng = 0; ng < 4; ng++) {
                    MMA_F16(acc[mt][ng], fAh[mt], fBh[ng]);
                    MMA_F16(acc[mt][ng], fAh[mt], fBl[ng]);
                    MMA_F16(acc[mt][ng], fAl[mt], fBh[ng]);
                }
            }
        }
        __syncthreads();
    }

    const int row0 = m0 + wr * 64 + lane / 4;
    const int col0 = wc * 32 + (lane % 4) * 2;
    #pragma unroll
    for (int mt = 0; mt < 4; mt++) {
        #pragma unroll
        for (int ng = 0; ng < 4; ng++) {
            int gc = n0 + col0 + ng * 8;
            if (SPLIT) {
                __half *Hp, *Lp;
                if (gc < 1024) { Hp = Ch; Lp = Cl; }
                else           { Hp = Dh; Lp = Dl; gc -= 1024; }
                size_t o1 = (size_t)(row0 + mt * 16) * DIM + gc;
                size_t o2 = o1 + 8 * DIM;
                uint32_t h, l;
                split2h(acc[mt][ng][0], acc[mt][ng][1], h, l);
                *(uint32_t*)(Hp + o1) = h;
                if (Lp) *(uint32_t*)(Lp + o1) = l;
                split2h(acc[mt][ng][2], acc[mt][ng][3], h, l);
                *(uint32_t*)(Hp + o2) = h;
                if (Lp) *(uint32_t*)(Lp + o2) = l;
            } else {
                size_t o1 = (size_t)(row0 + mt * 16) * DIM + gc;
                size_t o2 = o1 + 8 * DIM;
                *(float2*)(C + o1) = make_float2(acc[mt][ng][0], acc[mt][ng][1]);
                *(float2*)(C + o2) = make_float2(acc[mt][ng][2], acc[mt][ng][3]);
            }
        }
    }
}

// ---------------------------------------------------------------------------
// HMMA flash-attention (fp16 split): 128 Q-rows/CTA, chunked occ-2 pipeline.
// S = QK^T keeps the full 3-MMA split (logit precision load-bearing).
// PV is a SINGLE fp16 MMA (Ph*Vh): R15 measured 2.06e-3 for this cut in
// bf16; fp16 terms are 8x smaller -> ~2.6e-4 expected. Vl never exists.
// ---------------------------------------------------------------------------
#define AP 144
#define OFF_QH 0
#define OFF_QL 18432
#define OFF_KA 36864
#define OFF_KB 55296
#define OFF_VA 73728
#define OFF_VB 92160
#define OFF_MS 110592
#define ATTN_SMEM 111616
#define KHALF 9216

__global__ void __launch_bounds__(256, 2)
attn_hmma_kernel(const __half* __restrict__ Qh, const __half* __restrict__ Ql,
                 const __half* __restrict__ Kh, const __half* __restrict__ Kl,
                 const __half* __restrict__ Vh,
                 const int* __restrict__ maskp,
                 __half* __restrict__ Oh, __half* __restrict__ Ol)
{
    extern __shared__ __align__(128) char smc[];
    const uint32_t sb = smem_u32(smc);
    int* Msm = (int*)(smc + OFF_MS);

    const int t = threadIdx.x, wid = t >> 5, lane = t & 31;
    const int b = blockIdx.y >> 4, h = blockIdx.y & 15;
    const int n0 = blockIdx.x * 128;

    auto issueQ = [&]() {
        #pragma unroll
        for (int i = 0; i < 4; i++) {
            int idx = t + i * 256;
            int r = idx >> 3, ch = idx & 7;
            uint32_t doff = (uint32_t)(r * AP + ch * 16);
            size_t src = (size_t)(b * SEQ_N + n0 + r) * DIM + h * HD + ch * 8;
            CP_ASYNC16(sb + OFF_QH + doff, Qh + src);
            CP_ASYNC16(sb + OFF_QL + doff, Ql + src);
        }
        CP_COMMIT();
    };
    auto issueK = [&](int c, uint32_t off) {
        #pragma unroll
        for (int i = 0; i < 2; i++) {
            int idx = t + i * 256;
            int r = idx >> 3, ch = idx & 7;
            uint32_t doff = (uint32_t)(r * AP + ch * 16);
            size_t src = (size_t)(b * SEQ_M + c * 64 + r) * DIM + h * HD + ch * 8;
            CP_ASYNC16(sb + off + doff,         Kh + src);
            CP_ASYNC16(sb + off + KHALF + doff, Kl + src);
        }
        CP_COMMIT();
    };
    auto issueV = [&](int c, uint32_t off) {
        // V hi only (PV low terms dropped)
        #pragma unroll
        for (int i = 0; i < 2; i++) {
            int idx = t + i * 256;
            int r = idx >> 3, ch = idx & 7;
            uint32_t doff = (uint32_t)(r * AP + ch * 16);
            size_t src = (size_t)(b * SEQ_M + c * 64 + r) * DIM + h * HD + ch * 8;
            CP_ASYNC16(sb + off + doff, Vh + src);
        }
        CP_COMMIT();
    };

    issueQ();
    issueK(0, OFF_KA); issueV(0, OFF_VA);
    issueK(1, OFF_KB); issueV(1, OFF_VB);
    Msm[t] = maskp[b * SEQ_M + t];

    const int wm = wid;
    const int g = lane >> 3, lrw = lane & 7;
    const uint32_t a_off = (uint32_t)(((g & 1) * 8 + lrw) * AP + (g >> 1) * 16);
    const uint32_t b_off = (uint32_t)(((g >> 1) * 8 + lrw) * AP + (g & 1) * 16);

    float o[8][4];
    #pragma unroll
    for (int j = 0; j < 8; j++)
        #pragma unroll
        for (int q = 0; q < 4; q++) o[j][q] = 0.0f;
    float M1 = -INFINITY, M2 = -INFINITY, S1 = 0.0f, S2 = 0.0f;
    float acc[8][4];
    uint32_t qh_f[4][4], ql_f[4][4];
    const float scl2 = 0.125f * 1.4426950408889634f;

    auto computeS = [&](uint32_t ko) {
        #pragma unroll
        for (int j = 0; j < 8; j++)
            #pragma unroll
            for (int q = 0; q < 4; q++) acc[j][q] = 0.0f;
        #pragma unroll
        for (int ks = 0; ks < 4; ks++) {
            const uint32_t kb = (uint32_t)(ks * 32);
            #pragma unroll
            for (int nt = 0; nt < 4; nt++) {
                uint32_t krow = (uint32_t)(nt * 16) * AP + kb + b_off;
                uint32_t h0, h1, h2, h3, l0, l1, l2, l3;
                LDM_X4(h0, h1, h2, h3, sb + ko + krow);
                LDM_X4(l0, l1, l2, l3, sb + ko + KHALF + krow);
                uint32_t bh0[2] = {h0, h1}, bh1[2] = {h2, h3};
                uint32_t bl0[2] = {l0, l1}, bl1[2] = {l2, l3};
                MMA_F16(acc[nt * 2],     qh_f[ks], bh0);
                MMA_F16(acc[nt * 2],     qh_f[ks], bl0);
                MMA_F16(acc[nt * 2],     ql_f[ks], bh0);
                MMA_F16(acc[nt * 2 + 1], qh_f[ks], bh1);
                MMA_F16(acc[nt * 2 + 1], qh_f[ks], bl1);
                MMA_F16(acc[nt * 2 + 1], ql_f[ks], bh1);
            }
        }
    };

    auto softmaxPV = [&](int ci, uint32_t vo) {
        float m1 = -INFINITY, m2 = -INFINITY;
        #pragma unroll
        for (int j = 0; j < 8; j++) {
            int cb = ci * 64 + j * 8 + (lane & 3) * 2;
            bool k0 = Msm[cb] != 0, k1 = Msm[cb + 1] != 0;
            acc[j][0] = k0 ? acc[j][0] * scl2 : -1e30f;
            acc[j][1] = k1 ? acc[j][1] * scl2 : -1e30f;
            acc[j][2] = k0 ? acc[j][2] * scl2 : -1e30f;
            acc[j][3] = k1 ? acc[j][3] * scl2 : -1e30f;
            m1 = fmaxf(m1, fmaxf(acc[j][0], acc[j][1]));
            m2 = fmaxf(m2, fmaxf(acc[j][2], acc[j][3]));
        }
        m1 = fmaxf(m1, __shfl_xor_sync(0xffffffffu, m1, 1));
        m1 = fmaxf(m1, __shfl_xor_sync(0xffffffffu, m1, 2));
        m2 = fmaxf(m2, __shfl_xor_sync(0xffffffffu, m2, 1));
        m2 = fmaxf(m2, __shfl_xor_sync(0xffffffffu, m2, 2));

        float M1n = fmaxf(M1, m1), M2n = fmaxf(M2, m2);
        float sc1 = exp2f(M1 - M1n), sc2 = exp2f(M2 - M2n);
        #pragma unroll
        for (int j = 0; j < 8; j++) {
            o[j][0] *= sc1; o[j][1] *= sc1;
            o[j][2] *= sc2; o[j][3] *= sc2;
        }
        S1 *= sc1; S2 *= sc2;
        M1 = M1n; M2 = M2n;

        float s1 = 0.0f, s2 = 0.0f;
        #pragma unroll
        for (int j = 0; j < 8; j++) {
            acc[j][0] = exp2f(acc[j][0] - M1);
            acc[j][1] = exp2f(acc[j][1] - M1);
            acc[j][2] = exp2f(acc[j][2] - M2);
            acc[j][3] = exp2f(acc[j][3] - M2);
            s1 += acc[j][0] + acc[j][1];
            s2 += acc[j][2] + acc[j][3];
        }
        s1 += __shfl_xor_sync(0xffffffffu, s1, 1);
        s1 += __shfl_xor_sync(0xffffffffu, s1, 2);
        s2 += __shfl_xor_sync(0xffffffffu, s2, 1);
        s2 += __shfl_xor_sync(0xffffffffu, s2, 2);
        S1 += s1; S2 += s2;

        #pragma unroll
        for (int kk = 0; kk < 4; kk++) {
            const int j0 = kk * 2, j1 = j0 + 1;
            uint32_t ph[4];
            ph[0] = pack_h2(acc[j0][0], acc[j0][1]);
            ph[1] = pack_h2(acc[j0][2], acc[j0][3]);
            ph[2] = pack_h2(acc[j1][0], acc[j1][1]);
            ph[3] = pack_h2(acc[j1][2], acc[j1][3]);

            const uint32_t vrow = (uint32_t)(kk * 16 + (g & 1) * 8 + lrw) * AP;
            #pragma unroll
            for (int ngp = 0; ngp < 4; ngp++) {
                const uint32_t vcol = (uint32_t)(((g >> 1) * 8 + ngp * 16) * 2);
                uint32_t h0, h1, h2, h3;
                LDM_X4T(h0, h1, h2, h3, sb + vo + vrow + vcol);
                uint32_t vh0[2] = {h0, h1}, vh1[2] = {h2, h3};
                MMA_F16(o[ngp * 2],     ph, vh0);
                MMA_F16(o[ngp * 2 + 1], ph, vh1);
            }
        }
    };

    // --- pipelined mainloop (identical wait schedule to R16) ---
    CP_WAIT(3); __syncthreads();
    #pragma unroll
    for (int ks = 0; ks < 4; ks++) {
        const uint32_t kb = (uint32_t)(ks * 32);
        LDM_X4(qh_f[ks][0], qh_f[ks][1], qh_f[ks][2], qh_f[ks][3],
               sb + OFF_QH + (uint32_t)(wm * 16) * AP + kb + a_off);
        LDM_X4(ql_f[ks][0], ql_f[ks][1], ql_f[ks][2], ql_f[ks][3],
               sb + OFF_QL + (uint32_t)(wm * 16) * AP + kb + a_off);
    }
    computeS(OFF_KA);
    __syncthreads(); issueK(2, OFF_KA);
    CP_WAIT(3); __syncthreads();
    softmaxPV(0, OFF_VA);
    __syncthreads(); issueV(2, OFF_VA);
    CP_WAIT(3); __syncthreads();
    computeS(OFF_KB);
    __syncthreads(); issueK(3, OFF_KB);
    CP_WAIT(3); __syncthreads();
    softmaxPV(1, OFF_VB);
    __syncthreads(); issueV(3, OFF_VB);
    CP_WAIT(3); __syncthreads();
    computeS(OFF_KA);
    __syncthreads();
    CP_WAIT(2); __syncthreads();
    softmaxPV(2, OFF_VA);
    __syncthreads();
    CP_WAIT(1); __syncthreads();
    computeS(OFF_KB);
    CP_WAIT(0); __syncthreads();
    softmaxPV(3, OFF_VB);

    const float inv1 = 1.0f / S1, inv2 = 1.0f / S2;
    const int r1 = wm * 16 + (lane >> 2), r2 = r1 + 8;
    #pragma unroll
    for (int j = 0; j < 8; j++) {
        int col = j * 8 + (lane & 3) * 2;
        size_t go1 = (size_t)(b * SEQ_N + n0 + r1) * DIM + h * HD + col;
        size_t go2 = (size_t)(b * SEQ_N + n0 + r2) * DIM + h * HD + col;
        uint32_t hh, ll;
        split2h(o[j][0] * inv1, o[j][1] * inv1, hh, ll);
        *(uint32_t*)(Oh + go1) = hh; *(uint32_t*)(Ol + go1) = ll;
        split2h(o[j][2] * inv2, o[j][3] * inv2, hh, ll);
        *(uint32_t*)(Oh + go2) = hh; *(uint32_t*)(Ol + go2) = ll;
    }
}

// ---------------------------------------------------------------------------
// Host launcher — R12-proven two-stream fork/join schedule.
// ---------------------------------------------------------------------------
extern "C" void kernel_launch(void* const* d_in, const int* in_sizes, int n_in,
                              void* d_out, int out_size)
{
    const float* x    = (const float*)d_in[0];
    const float* ctx  = (const float*)d_in[1];
    const int*   mask = (const int*)d_in[2];
    const float* Wq   = (const float*)d_in[3];
    const float* Wk   = (const float*)d_in[4];
    const float* Wv   = (const float*)d_in[5];
    const float* Wo   = (const float*)d_in[6];
    float*       out  = (float*)d_out;

    __half *Ahp, *Alp, *Chp, *Clp, *Bqh, *Bql, *Bhp, *Blp, *Boh, *Bol;
    __half *Qhp, *Qlp, *Khp, *Klp, *Vhp;
    cudaGetSymbolAddress((void**)&Ahp, g_Ah);
    cudaGetSymbolAddress((void**)&Alp, g_Al);
    cudaGetSymbolAddress((void**)&Chp, g_Ch);
    cudaGetSymbolAddress((void**)&Clp, g_Cl);
    cudaGetSymbolAddress((void**)&Bqh, g_Bqh);
    cudaGetSymbolAddress((void**)&Bql, g_Bql);
    cudaGetSymbolAddress((void**)&Bhp, g_Bh);
    cudaGetSymbolAddress((void**)&Blp, g_Bl);
    cudaGetSymbolAddress((void**)&Boh, g_Boh);
    cudaGetSymbolAddress((void**)&Bol, g_Bol);
    cudaGetSymbolAddress((void**)&Qhp, g_Qh);
    cudaGetSymbolAddress((void**)&Qlp, g_Ql);
    cudaGetSymbolAddress((void**)&Khp, g_Kh);
    cudaGetSymbolAddress((void**)&Klp, g_Kl);
    cudaGetSymbolAddress((void**)&Vhp, g_Vh);

    cudaFuncSetAttribute(gemm_hmma_kernel<0>, cudaFuncAttributeMaxDynamicSharedMemorySize, GEMM_SMEM);
    cudaFuncSetAttribute(gemm_hmma_kernel<1>, cudaFuncAttributeMaxDynamicSharedMemorySize, GEMM_SMEM);
    cudaFuncSetAttribute(attn_hmma_kernel, cudaFuncAttributeMaxDynamicSharedMemorySize, ATTN_SMEM);

    static cudaStream_t s_aux = nullptr;
    static cudaEvent_t ev_fork = nullptr, ev_wq = nullptr, ev_kv = nullptr, ev_wo = nullptr;
    if (s_aux == nullptr) {
        cudaStreamCreateWithFlags(&s_aux, cudaStreamNonBlocking);
        cudaEventCreateWithFlags(&ev_fork, cudaEventDisableTiming);
        cudaEventCreateWithFlags(&ev_wq,   cudaEventDisableTiming);
        cudaEventCreateWithFlags(&ev_kv,   cudaEventDisableTiming);
        cudaEventCreateWithFlags(&ev_wo,   cudaEventDisableTiming);
    }

    const int n4x = ROWS_X * DIM / 4;
    const int n4c = ROWS_C * CTX_DIM / 4;
    dim3 tb32(32, 8);

    cudaEventRecord(ev_fork, 0);
    cudaStreamWaitEvent(s_aux, ev_fork, 0);

    // aux: Wq^T, KV chain, Wo^T
    transpose_split_kernel<<<dim3(DIM / 32, DIM / 32), tb32, 0, s_aux>>>(Wq, Bqh, Bql, DIM, DIM);
    cudaEventRecord(ev_wq, s_aux);
    split_kernel<<<n4c / 256, 256, 0, s_aux>>>(ctx, Chp, Clp, n4c);
    transpose_split_kernel<<<dim3(DIM / 32, CTX_DIM / 32), tb32, 0, s_aux>>>(Wk, Bhp, Blp, CTX_DIM, DIM);
    transpose_split_kernel<<<dim3(DIM / 32, CTX_DIM / 32), tb32, 0, s_aux>>>(
        Wv, Bhp + 1024 * CTX_DIM, Blp + 1024 * CTX_DIM, CTX_DIM, DIM);
    // Fused K|V projection. V goes to the D pair with Dl = nullptr (V low
    // half never used by attention). K keeps hi+lo.
    gemm_hmma_kernel<1><<<dim3(2048 / BN, ROWS_C / BM), 256, GEMM_SMEM, s_aux>>>(
        Chp, Clp, Bhp, Blp, nullptr, Khp, Klp, Vhp, nullptr, CTX_DIM);
    cudaEventRecord(ev_kv, s_aux);
    transpose_split_kernel<<<dim3(DIM / 32, DIM / 32), tb32, 0, s_aux>>>(Wo, Boh, Bol, DIM, DIM);
    cudaEventRecord(ev_wo, s_aux);

    // main: split x, Q projection, attention, O projection
    split_kernel<<<n4x / 256, 256>>>(x, Ahp, Alp, n4x);
    cudaStreamWaitEvent(0, ev_wq, 0);
    gemm_hmma_kernel<1><<<dim3(DIM / BN, ROWS_X / BM), 256, GEMM_SMEM>>>(
        Ahp, Alp, Bqh, Bql, nullptr, Qhp, Qlp, nullptr, nullptr, DIM);

    cudaStreamWaitEvent(0, ev_kv, 0);
    attn_hmma_kernel<<<dim3(SEQ_N / 128, BATCH * HEADS), 256, ATTN_SMEM>>>(
        Qhp, Qlp, Khp, Klp, Vhp, mask, Ahp, Alp);

    cudaStreamWaitEvent(0, ev_wo, 0);
    gemm_hmma_kernel<0><<<dim3(DIM / BN, ROWS_X / BM), 256, GEMM_SMEM>>>(
        Ahp, Alp, Boh, Bol, out, nullptr, nullptr, nullptr, nullptr, DIM);
}